// round 2
// baseline (speedup 1.0000x reference)
#include <cuda_runtime.h>
#include <cuda_fp16.h>
#include <math.h>

// Problem constants
#define B_   2
#define HH   56
#define WW   56
#define C_   256
#define NH   8
#define HD   32
#define TOK  (B_*HH*WW)      // 6272
#define POS  (HH*WW)         // 3136
#define QSCALE 0.17677669529663687f   // 32^-0.5

// Stage buffers (device globals — no runtime allocation).
// Q/K/V stored fp16 to halve attention gather traffic; attention output fp32.
__device__ __half g_q[B_*NH*POS*HD];
__device__ __half g_k[B_*NH*POS*HD];
__device__ __half g_v[B_*NH*POS*HD];
__device__ float  g_att[TOK*C_];

// ---------------------------------------------------------------------------
// fp32 GEMM: 128x128 block tile, BK=8, 256 threads, 8x8 per thread, float4 IO
// ---------------------------------------------------------------------------
__global__ __launch_bounds__(256) void qkv_gemm_kernel(const float* __restrict__ A,
                                                       const float* __restrict__ Bw,
                                                       const float* __restrict__ bias)
{
    __shared__ float As[8][132];
    __shared__ float Bs[8][128];

    const int tid  = threadIdx.x;
    const int row0 = blockIdx.y * 128;
    const int col0 = blockIdx.x * 128;
    const int K = C_;
    const int N = 3*C_;

    float acc[8][8];
    #pragma unroll
    for (int m = 0; m < 8; m++)
        #pragma unroll
        for (int n = 0; n < 8; n++)
            acc[m][n] = 0.0f;

    const int ar = (tid*4) / 8;     // row within A tile (0..127)
    const int ak = (tid*4) % 8;     // k offset (0 or 4)
    const int br = (tid*4) / 128;   // k row within B tile (0..7)
    const int bc = (tid*4) % 128;   // col within B tile
    const int ty = tid / 16;
    const int tx = tid % 16;

    for (int k0 = 0; k0 < K; k0 += 8) {
        float4 av = *(const float4*)&A[(long)(row0 + ar)*K + (k0 + ak)];
        As[ak+0][ar] = av.x;
        As[ak+1][ar] = av.y;
        As[ak+2][ar] = av.z;
        As[ak+3][ar] = av.w;
        *(float4*)&Bs[br][bc] = *(const float4*)&Bw[(long)(k0 + br)*N + (col0 + bc)];
        __syncthreads();

        #pragma unroll
        for (int kk = 0; kk < 8; kk++) {
            float ra[8], rb[8];
            *(float4*)&ra[0] = *(const float4*)&As[kk][ty*8];
            *(float4*)&ra[4] = *(const float4*)&As[kk][ty*8 + 4];
            *(float4*)&rb[0] = *(const float4*)&Bs[kk][tx*8];
            *(float4*)&rb[4] = *(const float4*)&Bs[kk][tx*8 + 4];
            #pragma unroll
            for (int m = 0; m < 8; m++)
                #pragma unroll
                for (int n = 0; n < 8; n++)
                    acc[m][n] += ra[m] * rb[n];
        }
        __syncthreads();
    }

    // Scatter: column j -> (t=j/256, h=(j/32)%8, d=j%32), fp16 stores
    #pragma unroll
    for (int m = 0; m < 8; m++) {
        int gm  = row0 + ty*8 + m;
        int b   = gm / POS;
        int pos = gm % POS;
        #pragma unroll
        for (int n = 0; n < 8; n++) {
            int gj = col0 + tx*8 + n;
            float v = acc[m][n] + bias[gj];
            int t = gj >> 8;
            int h = (gj >> 5) & 7;
            int d = gj & 31;
            long off = ((long)(b*NH + h)*POS + pos)*HD + d;
            if (t == 0)       g_q[off] = __float2half(v * QSCALE);
            else if (t == 1)  g_k[off] = __float2half(v);
            else              g_v[off] = __float2half(v);
        }
    }
}

__global__ __launch_bounds__(256) void proj_gemm_kernel(const float* __restrict__ Bw,
                                                        const float* __restrict__ bias,
                                                        float* __restrict__ Cout)
{
    __shared__ float As[8][132];
    __shared__ float Bs[8][128];

    const int tid  = threadIdx.x;
    const int row0 = blockIdx.y * 128;
    const int col0 = blockIdx.x * 128;
    const int K = C_;
    const int N = C_;

    float acc[8][8];
    #pragma unroll
    for (int m = 0; m < 8; m++)
        #pragma unroll
        for (int n = 0; n < 8; n++)
            acc[m][n] = 0.0f;

    const int ar = (tid*4) / 8;
    const int ak = (tid*4) % 8;
    const int br = (tid*4) / 128;
    const int bc = (tid*4) % 128;
    const int ty = tid / 16;
    const int tx = tid % 16;

    for (int k0 = 0; k0 < K; k0 += 8) {
        float4 av = *(const float4*)&g_att[(long)(row0 + ar)*K + (k0 + ak)];
        As[ak+0][ar] = av.x;
        As[ak+1][ar] = av.y;
        As[ak+2][ar] = av.z;
        As[ak+3][ar] = av.w;
        *(float4*)&Bs[br][bc] = *(const float4*)&Bw[(long)(k0 + br)*N + (col0 + bc)];
        __syncthreads();

        #pragma unroll
        for (int kk = 0; kk < 8; kk++) {
            float ra[8], rb[8];
            *(float4*)&ra[0] = *(const float4*)&As[kk][ty*8];
            *(float4*)&ra[4] = *(const float4*)&As[kk][ty*8 + 4];
            *(float4*)&rb[0] = *(const float4*)&Bs[kk][tx*8];
            *(float4*)&rb[4] = *(const float4*)&Bs[kk][tx*8 + 4];
            #pragma unroll
            for (int m = 0; m < 8; m++)
                #pragma unroll
                for (int n = 0; n < 8; n++)
                    acc[m][n] += ra[m] * rb[n];
        }
        __syncthreads();
    }

    #pragma unroll
    for (int m = 0; m < 8; m++) {
        int gm = row0 + ty*8 + m;
        #pragma unroll
        for (int n = 0; n < 8; n++) {
            int gj = col0 + tx*8 + n;
            Cout[(long)gm*N + gj] = acc[m][n] + bias[gj];
        }
    }
}

// ---------------------------------------------------------------------------
// Neighborhood attention: one warp per (token, head). lane = head-dim.
// K/V/Q in fp16 (64B per gathered vector), accumulation in fp32.
// ---------------------------------------------------------------------------
__global__ void natten_kernel(const float* __restrict__ rpb0,
                              const float* __restrict__ rpb1)
{
    const int m    = blockIdx.x;            // token index
    const int warp = threadIdx.x >> 5;      // head
    const int lane = threadIdx.x & 31;      // head-dim

    const int h   = warp;
    const int b   = m / POS;
    const int pos = m % POS;
    const int y   = pos / WW;
    const int x   = pos % WW;

    const int dil = (h < 4) ? 1 : 2;
    const float* __restrict__ rpb = (h < 4) ? rpb0 : rpb1;
    const int hh  = (h < 4) ? h : (h - 4);

    int nb_y[7], bi_y[7], nb_x[7], bi_x[7];
    {
        int r = y % dil, p = y / dil;
        int Lr = (HH - r + dil - 1) / dil;
        int ps = p - 3;
        if (ps < 0) ps = 0;
        if (ps > Lr - 7) ps = Lr - 7;
        #pragma unroll
        for (int a = 0; a < 7; a++) { nb_y[a] = (ps + a)*dil + r; bi_y[a] = a + (ps - p) + 6; }
    }
    {
        int r = x % dil, p = x / dil;
        int Lr = (WW - r + dil - 1) / dil;
        int ps = p - 3;
        if (ps < 0) ps = 0;
        if (ps > Lr - 7) ps = Lr - 7;
        #pragma unroll
        for (int a = 0; a < 7; a++) { nb_x[a] = (ps + a)*dil + r; bi_x[a] = a + (ps - p) + 6; }
    }

    const long base = (long)(b*NH + h) * POS * HD;
    const float qv = __half2float(g_q[base + (long)pos*HD + lane]);

    float l0 = -1e30f, l1 = -1e30f;

    #pragma unroll
    for (int i = 0; i < 7; i++) {
        #pragma unroll
        for (int j = 0; j < 7; j++) {
            int kp = nb_y[i]*WW + nb_x[j];
            float d = qv * __half2float(g_k[base + (long)kp*HD + lane]);
            #pragma unroll
            for (int s = 16; s; s >>= 1)
                d += __shfl_xor_sync(0xffffffffu, d, s);
            d += rpb[hh*169 + bi_y[i]*13 + bi_x[j]];
            int nb = i*7 + j;
            if (nb < 32) { if (lane == nb)      l0 = d; }
            else         { if (lane == nb - 32) l1 = d; }
        }
    }

    // softmax over 49 logits
    float mx = fmaxf(l0, l1);
    #pragma unroll
    for (int s = 16; s; s >>= 1)
        mx = fmaxf(mx, __shfl_xor_sync(0xffffffffu, mx, s));

    float p0 = __expf(l0 - mx);
    float p1 = __expf(l1 - mx);   // -1e30 -> 0

    float sum = p0 + p1;
    #pragma unroll
    for (int s = 16; s; s >>= 1)
        sum += __shfl_xor_sync(0xffffffffu, sum, s);
    const float inv = 1.0f / sum;

    float acc = 0.0f;
    #pragma unroll
    for (int nb = 0; nb < 49; nb++) {
        int i = nb / 7, j = nb % 7;
        int kp = nb_y[i]*WW + nb_x[j];
        float pv = (nb < 32) ? p0 : p1;
        float p  = __shfl_sync(0xffffffffu, pv, nb & 31);
        acc += p * __half2float(g_v[base + (long)kp*HD + lane]);
    }

    g_att[(long)(b*POS + pos)*C_ + h*HD + lane] = acc * inv;
}

// ---------------------------------------------------------------------------
extern "C" void kernel_launch(void* const* d_in, const int* in_sizes, int n_in,
                              void* d_out, int out_size)
{
    const float* x      = (const float*)d_in[0];
    const float* w_qkv  = (const float*)d_in[1];
    const float* b_qkv  = (const float*)d_in[2];
    const float* w_proj = (const float*)d_in[3];
    const float* b_proj = (const float*)d_in[4];
    const float* rpb0   = (const float*)d_in[5];
    const float* rpb1   = (const float*)d_in[6];
    float* out = (float*)d_out;

    dim3 blk(256);
    dim3 grid_qkv((3*C_)/128, TOK/128);   // (6, 49)
    dim3 grid_proj(C_/128,    TOK/128);   // (2, 49)

    qkv_gemm_kernel<<<grid_qkv, blk>>>(x, w_qkv, b_qkv);
    natten_kernel<<<TOK, 256>>>(rpb0, rpb1);
    proj_gemm_kernel<<<grid_proj, blk>>>(w_proj, b_proj, out);
}

// round 4
// speedup vs baseline: 1.8109x; 1.8109x over previous
#include <cuda_runtime.h>
#include <math.h>

// Problem constants
#define B_   2
#define HH   56
#define WW   56
#define C_   256
#define NH   8
#define HD   32
#define TOK  (B_*HH*WW)      // 6272
#define POS  (HH*WW)         // 3136
#define QSCALE 0.17677669529663687f   // 32^-0.5

// Stage buffers (device globals — no runtime allocation), all fp32.
__device__ float g_q[B_*NH*POS*HD];
__device__ float g_k[B_*NH*POS*HD];
__device__ float g_v[B_*NH*POS*HD];
__device__ float g_att[TOK*C_];

// ---------------------------------------------------------------------------
// fp32 GEMM: 128x128 block tile, BK=8, 256 threads, 8x8 per thread, float4 IO
// ---------------------------------------------------------------------------
__global__ __launch_bounds__(256) void qkv_gemm_kernel(const float* __restrict__ A,
                                                       const float* __restrict__ Bw,
                                                       const float* __restrict__ bias)
{
    __shared__ alignas(16) float As[8][132];
    __shared__ alignas(16) float Bs[8][128];

    const int tid  = threadIdx.x;
    const int row0 = blockIdx.y * 128;
    const int col0 = blockIdx.x * 128;
    const int K = C_;
    const int N = 3*C_;

    float acc[8][8];
    #pragma unroll
    for (int m = 0; m < 8; m++)
        #pragma unroll
        for (int n = 0; n < 8; n++)
            acc[m][n] = 0.0f;

    const int ar = (tid*4) / 8;
    const int ak = (tid*4) % 8;
    const int br = (tid*4) / 128;
    const int bc = (tid*4) % 128;
    const int ty = tid / 16;
    const int tx = tid % 16;

    for (int k0 = 0; k0 < K; k0 += 8) {
        float4 av = *(const float4*)&A[(long)(row0 + ar)*K + (k0 + ak)];
        As[ak+0][ar] = av.x;
        As[ak+1][ar] = av.y;
        As[ak+2][ar] = av.z;
        As[ak+3][ar] = av.w;
        *(float4*)&Bs[br][bc] = *(const float4*)&Bw[(long)(k0 + br)*N + (col0 + bc)];
        __syncthreads();

        #pragma unroll
        for (int kk = 0; kk < 8; kk++) {
            float ra[8], rb[8];
            *(float4*)&ra[0] = *(const float4*)&As[kk][ty*8];
            *(float4*)&ra[4] = *(const float4*)&As[kk][ty*8 + 4];
            *(float4*)&rb[0] = *(const float4*)&Bs[kk][tx*8];
            *(float4*)&rb[4] = *(const float4*)&Bs[kk][tx*8 + 4];
            #pragma unroll
            for (int m = 0; m < 8; m++)
                #pragma unroll
                for (int n = 0; n < 8; n++)
                    acc[m][n] += ra[m] * rb[n];
        }
        __syncthreads();
    }

    #pragma unroll
    for (int m = 0; m < 8; m++) {
        int gm  = row0 + ty*8 + m;
        int b   = gm / POS;
        int pos = gm % POS;
        #pragma unroll
        for (int n = 0; n < 8; n++) {
            int gj = col0 + tx*8 + n;
            float v = acc[m][n] + bias[gj];
            int t = gj >> 8;
            int h = (gj >> 5) & 7;
            int d = gj & 31;
            long off = ((long)(b*NH + h)*POS + pos)*HD + d;
            if (t == 0)       g_q[off] = v * QSCALE;
            else if (t == 1)  g_k[off] = v;
            else              g_v[off] = v;
        }
    }
}

__global__ __launch_bounds__(256) void proj_gemm_kernel(const float* __restrict__ Bw,
                                                        const float* __restrict__ bias,
                                                        float* __restrict__ Cout)
{
    __shared__ alignas(16) float As[8][132];
    __shared__ alignas(16) float Bs[8][128];

    const int tid  = threadIdx.x;
    const int row0 = blockIdx.y * 128;
    const int col0 = blockIdx.x * 128;
    const int K = C_;
    const int N = C_;

    float acc[8][8];
    #pragma unroll
    for (int m = 0; m < 8; m++)
        #pragma unroll
        for (int n = 0; n < 8; n++)
            acc[m][n] = 0.0f;

    const int ar = (tid*4) / 8;
    const int ak = (tid*4) % 8;
    const int br = (tid*4) / 128;
    const int bc = (tid*4) % 128;
    const int ty = tid / 16;
    const int tx = tid % 16;

    for (int k0 = 0; k0 < K; k0 += 8) {
        float4 av = *(const float4*)&g_att[(long)(row0 + ar)*K + (k0 + ak)];
        As[ak+0][ar] = av.x;
        As[ak+1][ar] = av.y;
        As[ak+2][ar] = av.z;
        As[ak+3][ar] = av.w;
        *(float4*)&Bs[br][bc] = *(const float4*)&Bw[(long)(k0 + br)*N + (col0 + bc)];
        __syncthreads();

        #pragma unroll
        for (int kk = 0; kk < 8; kk++) {
            float ra[8], rb[8];
            *(float4*)&ra[0] = *(const float4*)&As[kk][ty*8];
            *(float4*)&ra[4] = *(const float4*)&As[kk][ty*8 + 4];
            *(float4*)&rb[0] = *(const float4*)&Bs[kk][tx*8];
            *(float4*)&rb[4] = *(const float4*)&Bs[kk][tx*8 + 4];
            #pragma unroll
            for (int m = 0; m < 8; m++)
                #pragma unroll
                for (int n = 0; n < 8; n++)
                    acc[m][n] += ra[m] * rb[n];
        }
        __syncthreads();
    }

    #pragma unroll
    for (int m = 0; m < 8; m++) {
        int gm = row0 + ty*8 + m;
        #pragma unroll
        for (int n = 0; n < 8; n++) {
            int gj = col0 + tx*8 + n;
            Cout[(long)gm*N + gj] = acc[m][n] + bias[gj];
        }
    }
}

// ---------------------------------------------------------------------------
// Tiled neighborhood attention.
// dil=2 decomposes into 4 independent 28x28 dil=1 sub-images (y,x parity).
// Block = one 7x7 query tile of one (b, head, sub-image). 13x13 K/V halo in
// smem. Warp processes queries: lane=neighbor for logits, lane=dim for AV.
// Grid: (64, NH, B_), 128 threads.
// ---------------------------------------------------------------------------
#define HALO 13
#define NROW (HALO*HALO)   // 169
#define KSTR 33            // padded K row stride (conflict avoidance)

__global__ __launch_bounds__(128) void natten_kernel(const float* __restrict__ rpb0,
                                                     const float* __restrict__ rpb1)
{
    __shared__ alignas(16) float Ks[NROW*KSTR];  // 22308 B
    __shared__ alignas(16) float Vs[NROW*HD];    // 21632 B
    __shared__ alignas(16) float Rs[NROW];       //   676 B

    const int b = blockIdx.z;
    const int h = blockIdx.y;
    const int dil = (h < 4) ? 1 : 2;
    const float* __restrict__ rpb = (h < 4) ? (rpb0 + h*NROW) : (rpb1 + (h-4)*NROW);

    int ry, rx, qy0, qx0, L;
    if (dil == 1) {
        L = 56; ry = 0; rx = 0;
        qy0 = (blockIdx.x >> 3) * 7;
        qx0 = (blockIdx.x & 7) * 7;
    } else {
        L = 28;
        int sub = blockIdx.x >> 4;
        ry = sub >> 1; rx = sub & 1;
        int ti = blockIdx.x & 15;
        qy0 = (ti >> 2) * 7;
        qx0 = (ti & 3) * 7;
    }

    int hy0 = qy0 - 3; if (hy0 < 0) hy0 = 0; if (hy0 > L - HALO) hy0 = L - HALO;
    int hx0 = qx0 - 3; if (hx0 < 0) hx0 = 0; if (hx0 > L - HALO) hx0 = L - HALO;

    const long base = ((long)(b*NH + h)) * POS * HD;
    const int tid = threadIdx.x;

    // Load K/V halo: 169 rows of 32 floats (float4 per 8 lanes per row).
    {
        const int tr = tid >> 3;        // 0..15
        const int c  = (tid & 7) * 4;   // float4 column
        for (int t0 = 0; t0 < NROW; t0 += 16) {
            int t = t0 + tr;
            if (t < NROW) {
                int iy = t / HALO, ix = t % HALO;
                int gy = (hy0 + iy)*dil + ry;
                int gx = (hx0 + ix)*dil + rx;
                long off = base + (long)(gy*WW + gx)*HD + c;
                float4 kv = *(const float4*)&g_k[off];
                Ks[t*KSTR + c + 0] = kv.x;
                Ks[t*KSTR + c + 1] = kv.y;
                Ks[t*KSTR + c + 2] = kv.z;
                Ks[t*KSTR + c + 3] = kv.w;
                float4 vv = *(const float4*)&g_v[off];
                *(float4*)&Vs[t*HD + c] = vv;
            }
        }
    }
    for (int t = tid; t < NROW; t += 128) Rs[t] = rpb[t];
    __syncthreads();

    const int w    = tid >> 5;
    const int lane = tid & 31;

    const int n1 = lane;
    const int i1 = n1 / 7, j1 = n1 % 7;
    const bool has2 = (lane < 17);
    const int n2 = 32 + lane;
    const int i2 = has2 ? n2 / 7 : 0;
    const int j2 = has2 ? n2 % 7 : 0;

    for (int t = 0; t < 13; t++) {
        int q = w + 4*t;
        if (q >= 49) break;
        int qy = qy0 + q / 7;
        int qx = qx0 + q % 7;

        int wsy = qy - 3; if (wsy < 0) wsy = 0; if (wsy > L-7) wsy = L-7;
        int wsx = qx - 3; if (wsx < 0) wsx = 0; if (wsx > L-7) wsx = L-7;
        int oy = wsy - hy0, ox = wsx - hx0;
        int biy = wsy - qy + 6, bix = wsx - qx + 6;

        int gy = qy*dil + ry;
        int gx = qx*dil + rx;

        float qreg = g_q[base + (long)(gy*WW + gx)*HD + lane];

        const float* k1 = &Ks[((oy + i1)*HALO + ox + j1) * KSTR];
        const float* k2 = &Ks[((oy + i2)*HALO + ox + j2) * KSTR];

        float a1 = 0.0f, a2 = 0.0f;
        #pragma unroll
        for (int d = 0; d < 32; d++) {
            float qd = __shfl_sync(0xffffffffu, qreg, d);
            a1 += qd * k1[d];
            a2 += qd * k2[d];
        }

        float l0 = a1 + Rs[(biy + i1)*HALO + bix + j1];
        float l1 = has2 ? (a2 + Rs[(biy + i2)*HALO + bix + j2]) : -1e30f;

        float mx = fmaxf(l0, l1);
        #pragma unroll
        for (int s = 16; s; s >>= 1)
            mx = fmaxf(mx, __shfl_xor_sync(0xffffffffu, mx, s));

        float p0 = __expf(l0 - mx);
        float p1 = has2 ? __expf(l1 - mx) : 0.0f;

        float sum = p0 + p1;
        #pragma unroll
        for (int s = 16; s; s >>= 1)
            sum += __shfl_xor_sync(0xffffffffu, sum, s);
        float inv = 1.0f / sum;

        float acc = 0.0f;
        #pragma unroll
        for (int n = 0; n < 49; n++) {
            const int ni = n / 7, nj = n % 7;
            int rr = (oy + ni)*HALO + ox + nj;
            float pv = (n < 32) ? p0 : p1;
            float p = __shfl_sync(0xffffffffu, pv, n & 31);
            acc += p * Vs[rr*HD + lane];
        }

        g_att[((long)(b*POS) + gy*WW + gx)*C_ + h*HD + lane] = acc * inv;
    }
}

// ---------------------------------------------------------------------------
extern "C" void kernel_launch(void* const* d_in, const int* in_sizes, int n_in,
                              void* d_out, int out_size)
{
    const float* x      = (const float*)d_in[0];
    const float* w_qkv  = (const float*)d_in[1];
    const float* b_qkv  = (const float*)d_in[2];
    const float* w_proj = (const float*)d_in[3];
    const float* b_proj = (const float*)d_in[4];
    const float* rpb0   = (const float*)d_in[5];
    const float* rpb1   = (const float*)d_in[6];
    float* out = (float*)d_out;

    dim3 blk(256);
    dim3 grid_qkv((3*C_)/128, TOK/128);   // (6, 49)
    dim3 grid_proj(C_/128,    TOK/128);   // (2, 49)

    qkv_gemm_kernel<<<grid_qkv, blk>>>(x, w_qkv, b_qkv);
    natten_kernel<<<dim3(64, NH, B_), 128>>>(rpb0, rpb1);
    proj_gemm_kernel<<<grid_proj, blk>>>(w_proj, b_proj, out);
}

// round 5
// speedup vs baseline: 3.1481x; 1.7385x over previous
#include <cuda_runtime.h>
#include <math.h>

// Problem constants
#define B_   2
#define HH   56
#define WW   56
#define C_   256
#define NH   8
#define HD   32
#define TOK  (B_*HH*WW)      // 6272
#define POS  (HH*WW)         // 3136
#define QSCALE 0.17677669529663687f   // 32^-0.5

// Stage buffers (device globals — no runtime allocation), all fp32.
__device__ float g_q[B_*NH*POS*HD];
__device__ float g_k[B_*NH*POS*HD];
__device__ float g_v[B_*NH*POS*HD];
__device__ float g_att[TOK*C_];

__device__ __forceinline__ unsigned f2tf32(float f) {
    unsigned u;
    asm("cvt.rna.tf32.f32 %0, %1;" : "=r"(u) : "f"(f));
    return u;
}

// ---------------------------------------------------------------------------
// tf32 tensor-core GEMM: C[M,N] = A[M,256] @ B[256,N] + bias
// Block tile 128x128, BK=16, 256 threads = 8 warps (4x2), warp tile 32x64.
// mma.sync.aligned.m16n8k8.row.col.f32.tf32.tf32.f32
// mode 0: qkv scatter into g_q/g_k/g_v   mode 1: plain store to Cout
// A==nullptr means read from g_att.
// ---------------------------------------------------------------------------
#define ASTR 20    // A smem row stride (floats): banks (20r+c)%32 distinct
#define BSTR 136   // B smem row stride (floats): banks (8k+g)%32 distinct

__global__ __launch_bounds__(256) void gemm_tf32_kernel(
    const float* __restrict__ A, const float* __restrict__ Bw,
    const float* __restrict__ bias, float* __restrict__ Cout,
    int N, int mode)
{
    __shared__ alignas(16) unsigned As[128*ASTR];
    __shared__ alignas(16) unsigned Bs[16*BSTR];

    const float* __restrict__ Ap = A ? A : g_att;

    const int tid  = threadIdx.x;
    const int lane = tid & 31;
    const int w    = tid >> 5;
    const int wm   = w >> 1;         // 0..3
    const int wn   = w & 1;          // 0..1
    const int g    = lane >> 2;      // groupID 0..7
    const int tg   = lane & 3;       // thread-in-group 0..3

    const int row0 = blockIdx.y * 128;
    const int col0 = blockIdx.x * 128;

    float c[2][8][4];
    #pragma unroll
    for (int mt = 0; mt < 2; mt++)
        #pragma unroll
        for (int nt = 0; nt < 8; nt++)
            #pragma unroll
            for (int i = 0; i < 4; i++)
                c[mt][nt][i] = 0.0f;

    for (int k0 = 0; k0 < 256; k0 += 16) {
        // Load+convert A tile: 128x16
        #pragma unroll
        for (int j = 0; j < 2; j++) {
            int idx = tid + j*256;
            int r  = idx >> 2;
            int cc = (idx & 3) << 2;
            float4 v = *(const float4*)&Ap[(long)(row0 + r)*256 + k0 + cc];
            uint4 u;
            u.x = f2tf32(v.x); u.y = f2tf32(v.y);
            u.z = f2tf32(v.z); u.w = f2tf32(v.w);
            *(uint4*)&As[r*ASTR + cc] = u;
        }
        // Load+convert B tile: 16x128
        #pragma unroll
        for (int j = 0; j < 2; j++) {
            int idx = tid + j*256;
            int r  = idx >> 5;
            int cc = (idx & 31) << 2;
            float4 v = *(const float4*)&Bw[(long)(k0 + r)*N + col0 + cc];
            uint4 u;
            u.x = f2tf32(v.x); u.y = f2tf32(v.y);
            u.z = f2tf32(v.z); u.w = f2tf32(v.w);
            *(uint4*)&Bs[r*BSTR + cc] = u;
        }
        __syncthreads();

        #pragma unroll
        for (int kc = 0; kc < 16; kc += 8) {
            unsigned a[2][4], bf[8][2];
            #pragma unroll
            for (int mt = 0; mt < 2; mt++) {
                int rb = wm*32 + mt*16;
                a[mt][0] = As[(rb + g    )*ASTR + kc + tg    ];
                a[mt][1] = As[(rb + g + 8)*ASTR + kc + tg    ];
                a[mt][2] = As[(rb + g    )*ASTR + kc + tg + 4];
                a[mt][3] = As[(rb + g + 8)*ASTR + kc + tg + 4];
            }
            #pragma unroll
            for (int nt = 0; nt < 8; nt++) {
                int cb = wn*64 + nt*8;
                bf[nt][0] = Bs[(kc + tg    )*BSTR + cb + g];
                bf[nt][1] = Bs[(kc + tg + 4)*BSTR + cb + g];
            }
            #pragma unroll
            for (int mt = 0; mt < 2; mt++)
                #pragma unroll
                for (int nt = 0; nt < 8; nt++)
                    asm volatile(
                        "mma.sync.aligned.m16n8k8.row.col.f32.tf32.tf32.f32 "
                        "{%0,%1,%2,%3}, {%4,%5,%6,%7}, {%8,%9}, {%0,%1,%2,%3};"
                        : "+f"(c[mt][nt][0]), "+f"(c[mt][nt][1]),
                          "+f"(c[mt][nt][2]), "+f"(c[mt][nt][3])
                        : "r"(a[mt][0]), "r"(a[mt][1]), "r"(a[mt][2]), "r"(a[mt][3]),
                          "r"(bf[nt][0]), "r"(bf[nt][1]));
        }
        __syncthreads();
    }

    // Epilogue
    #pragma unroll
    for (int mt = 0; mt < 2; mt++) {
        int r_lo = row0 + wm*32 + mt*16 + g;
        int r_hi = r_lo + 8;
        #pragma unroll
        for (int nt = 0; nt < 8; nt++) {
            int gj = col0 + wn*64 + nt*8 + 2*tg;
            float b0 = bias[gj], b1 = bias[gj+1];
            if (mode == 1) {
                Cout[(long)r_lo*N + gj    ] = c[mt][nt][0] + b0;
                Cout[(long)r_lo*N + gj + 1] = c[mt][nt][1] + b1;
                Cout[(long)r_hi*N + gj    ] = c[mt][nt][2] + b0;
                Cout[(long)r_hi*N + gj + 1] = c[mt][nt][3] + b1;
            } else {
                int t = gj >> 8;
                int h = (gj >> 5) & 7;
                int d = gj & 31;
                #pragma unroll
                for (int e = 0; e < 4; e++) {
                    int gm = (e < 2) ? r_lo : r_hi;
                    float v = c[mt][nt][e] + ((e & 1) ? b1 : b0);
                    int bb  = gm / POS;
                    int pos = gm % POS;
                    long off = ((long)(bb*NH + h)*POS + pos)*HD + d + (e & 1);
                    if (t == 0)       g_q[off] = v * QSCALE;
                    else if (t == 1)  g_k[off] = v;
                    else              g_v[off] = v;
                }
            }
        }
    }
}

// ---------------------------------------------------------------------------
// Tiled neighborhood attention (unchanged from R4 — verified 3.1e-7).
// ---------------------------------------------------------------------------
#define HALO 13
#define NROW (HALO*HALO)   // 169
#define KSTR 33

__global__ __launch_bounds__(128) void natten_kernel(const float* __restrict__ rpb0,
                                                     const float* __restrict__ rpb1)
{
    __shared__ alignas(16) float Ks[NROW*KSTR];
    __shared__ alignas(16) float Vs[NROW*HD];
    __shared__ alignas(16) float Rs[NROW];

    const int b = blockIdx.z;
    const int h = blockIdx.y;
    const int dil = (h < 4) ? 1 : 2;
    const float* __restrict__ rpb = (h < 4) ? (rpb0 + h*NROW) : (rpb1 + (h-4)*NROW);

    int ry, rx, qy0, qx0, L;
    if (dil == 1) {
        L = 56; ry = 0; rx = 0;
        qy0 = (blockIdx.x >> 3) * 7;
        qx0 = (blockIdx.x & 7) * 7;
    } else {
        L = 28;
        int sub = blockIdx.x >> 4;
        ry = sub >> 1; rx = sub & 1;
        int ti = blockIdx.x & 15;
        qy0 = (ti >> 2) * 7;
        qx0 = (ti & 3) * 7;
    }

    int hy0 = qy0 - 3; if (hy0 < 0) hy0 = 0; if (hy0 > L - HALO) hy0 = L - HALO;
    int hx0 = qx0 - 3; if (hx0 < 0) hx0 = 0; if (hx0 > L - HALO) hx0 = L - HALO;

    const long base = ((long)(b*NH + h)) * POS * HD;
    const int tid = threadIdx.x;

    {
        const int tr = tid >> 3;
        const int c  = (tid & 7) * 4;
        for (int t0 = 0; t0 < NROW; t0 += 16) {
            int t = t0 + tr;
            if (t < NROW) {
                int iy = t / HALO, ix = t % HALO;
                int gy = (hy0 + iy)*dil + ry;
                int gx = (hx0 + ix)*dil + rx;
                long off = base + (long)(gy*WW + gx)*HD + c;
                float4 kv = *(const float4*)&g_k[off];
                Ks[t*KSTR + c + 0] = kv.x;
                Ks[t*KSTR + c + 1] = kv.y;
                Ks[t*KSTR + c + 2] = kv.z;
                Ks[t*KSTR + c + 3] = kv.w;
                float4 vv = *(const float4*)&g_v[off];
                *(float4*)&Vs[t*HD + c] = vv;
            }
        }
    }
    for (int t = tid; t < NROW; t += 128) Rs[t] = rpb[t];
    __syncthreads();

    const int w    = tid >> 5;
    const int lane = tid & 31;

    const int n1 = lane;
    const int i1 = n1 / 7, j1 = n1 % 7;
    const bool has2 = (lane < 17);
    const int n2 = 32 + lane;
    const int i2 = has2 ? n2 / 7 : 0;
    const int j2 = has2 ? n2 % 7 : 0;

    for (int t = 0; t < 13; t++) {
        int q = w + 4*t;
        if (q >= 49) break;
        int qy = qy0 + q / 7;
        int qx = qx0 + q % 7;

        int wsy = qy - 3; if (wsy < 0) wsy = 0; if (wsy > L-7) wsy = L-7;
        int wsx = qx - 3; if (wsx < 0) wsx = 0; if (wsx > L-7) wsx = L-7;
        int oy = wsy - hy0, ox = wsx - hx0;
        int biy = wsy - qy + 6, bix = wsx - qx + 6;

        int gy = qy*dil + ry;
        int gx = qx*dil + rx;

        float qreg = g_q[base + (long)(gy*WW + gx)*HD + lane];

        const float* k1 = &Ks[((oy + i1)*HALO + ox + j1) * KSTR];
        const float* k2 = &Ks[((oy + i2)*HALO + ox + j2) * KSTR];

        float a1 = 0.0f, a2 = 0.0f;
        #pragma unroll
        for (int d = 0; d < 32; d++) {
            float qd = __shfl_sync(0xffffffffu, qreg, d);
            a1 += qd * k1[d];
            a2 += qd * k2[d];
        }

        float l0 = a1 + Rs[(biy + i1)*HALO + bix + j1];
        float l1 = has2 ? (a2 + Rs[(biy + i2)*HALO + bix + j2]) : -1e30f;

        float mx = fmaxf(l0, l1);
        #pragma unroll
        for (int s = 16; s; s >>= 1)
            mx = fmaxf(mx, __shfl_xor_sync(0xffffffffu, mx, s));

        float p0 = __expf(l0 - mx);
        float p1 = has2 ? __expf(l1 - mx) : 0.0f;

        float sum = p0 + p1;
        #pragma unroll
        for (int s = 16; s; s >>= 1)
            sum += __shfl_xor_sync(0xffffffffu, sum, s);
        float inv = 1.0f / sum;

        float acc = 0.0f;
        #pragma unroll
        for (int n = 0; n < 49; n++) {
            const int ni = n / 7, nj = n % 7;
            int rr = (oy + ni)*HALO + ox + nj;
            float pv = (n < 32) ? p0 : p1;
            float p = __shfl_sync(0xffffffffu, pv, n & 31);
            acc += p * Vs[rr*HD + lane];
        }

        g_att[((long)(b*POS) + gy*WW + gx)*C_ + h*HD + lane] = acc * inv;
    }
}

// ---------------------------------------------------------------------------
extern "C" void kernel_launch(void* const* d_in, const int* in_sizes, int n_in,
                              void* d_out, int out_size)
{
    const float* x      = (const float*)d_in[0];
    const float* w_qkv  = (const float*)d_in[1];
    const float* b_qkv  = (const float*)d_in[2];
    const float* w_proj = (const float*)d_in[3];
    const float* b_proj = (const float*)d_in[4];
    const float* rpb0   = (const float*)d_in[5];
    const float* rpb1   = (const float*)d_in[6];
    float* out = (float*)d_out;

    dim3 blk(256);
    dim3 grid_qkv((3*C_)/128, TOK/128);   // (6, 49)
    dim3 grid_proj(C_/128,    TOK/128);   // (2, 49)

    gemm_tf32_kernel<<<grid_qkv, blk>>>(x, w_qkv, b_qkv, nullptr, 3*C_, 0);
    natten_kernel<<<dim3(64, NH, B_), 128>>>(rpb0, rpb1);
    gemm_tf32_kernel<<<grid_proj, blk>>>(nullptr, w_proj, b_proj, out, C_, 1);
}

// round 6
// speedup vs baseline: 3.5208x; 1.1184x over previous
#include <cuda_runtime.h>
#include <math.h>

// Problem constants
#define B_   2
#define HH   56
#define WW   56
#define C_   256
#define NH   8
#define HD   32
#define TOK  (B_*HH*WW)      // 6272
#define POS  (HH*WW)         // 3136
#define QSCALE 0.17677669529663687f   // 32^-0.5

__device__ float g_q[B_*NH*POS*HD];
__device__ float g_k[B_*NH*POS*HD];
__device__ float g_v[B_*NH*POS*HD];
__device__ float g_att[TOK*C_];

__device__ __forceinline__ unsigned f2tf32(float f) {
    unsigned u;
    asm("cvt.rna.tf32.f32 %0, %1;" : "=r"(u) : "f"(f));
    return u;
}

// ---------------------------------------------------------------------------
// tf32 tensor-core GEMM, double-buffered software pipeline.
// Block tile 128x128, BK=16, 256 threads = 8 warps (4x2), warp tile 32x64.
// ---------------------------------------------------------------------------
#define ASTR 20
#define BSTR 136
#define NKT  16    // 256/16 K-tiles

__global__ __launch_bounds__(256) void gemm_tf32_kernel(
    const float* __restrict__ A, const float* __restrict__ Bw,
    const float* __restrict__ bias, float* __restrict__ Cout,
    int N, int mode)
{
    __shared__ alignas(16) unsigned As[2][128*ASTR];
    __shared__ alignas(16) unsigned Bs[2][16*BSTR];

    const float* __restrict__ Ap = A ? A : g_att;

    const int tid  = threadIdx.x;
    const int lane = tid & 31;
    const int w    = tid >> 5;
    const int wm   = w >> 1;
    const int wn   = w & 1;
    const int g    = lane >> 2;
    const int tg   = lane & 3;

    const int row0 = blockIdx.y * 128;
    const int col0 = blockIdx.x * 128;

    // per-thread load coords
    const int a_r0 = tid >> 2,          a_c0 = (tid & 3) << 2;
    const int a_r1 = (tid + 256) >> 2,  a_c1 = a_c0;
    const int b_r0 = tid >> 5,          b_c0 = (tid & 31) << 2;
    const int b_r1 = (tid + 256) >> 5,  b_c1 = b_c0;

    float c[2][8][4];
    #pragma unroll
    for (int mt = 0; mt < 2; mt++)
        #pragma unroll
        for (int nt = 0; nt < 8; nt++)
            #pragma unroll
            for (int i = 0; i < 4; i++)
                c[mt][nt][i] = 0.0f;

    float4 sa0, sa1, sb0, sb1;

    // prologue: load tile 0, convert, store to buf 0
    sa0 = *(const float4*)&Ap[(long)(row0 + a_r0)*256 + a_c0];
    sa1 = *(const float4*)&Ap[(long)(row0 + a_r1)*256 + a_c1];
    sb0 = *(const float4*)&Bw[(long)b_r0*N + col0 + b_c0];
    sb1 = *(const float4*)&Bw[(long)b_r1*N + col0 + b_c1];
    {
        uint4 u;
        u.x=f2tf32(sa0.x); u.y=f2tf32(sa0.y); u.z=f2tf32(sa0.z); u.w=f2tf32(sa0.w);
        *(uint4*)&As[0][a_r0*ASTR + a_c0] = u;
        u.x=f2tf32(sa1.x); u.y=f2tf32(sa1.y); u.z=f2tf32(sa1.z); u.w=f2tf32(sa1.w);
        *(uint4*)&As[0][a_r1*ASTR + a_c1] = u;
        u.x=f2tf32(sb0.x); u.y=f2tf32(sb0.y); u.z=f2tf32(sb0.z); u.w=f2tf32(sb0.w);
        *(uint4*)&Bs[0][b_r0*BSTR + b_c0] = u;
        u.x=f2tf32(sb1.x); u.y=f2tf32(sb1.y); u.z=f2tf32(sb1.z); u.w=f2tf32(sb1.w);
        *(uint4*)&Bs[0][b_r1*BSTR + b_c1] = u;
    }
    __syncthreads();

    #pragma unroll
    for (int kt = 0; kt < NKT; kt++) {
        const int cur = kt & 1;
        const int nxt = cur ^ 1;

        if (kt < NKT-1) {
            int k0 = (kt+1) * 16;
            sa0 = *(const float4*)&Ap[(long)(row0 + a_r0)*256 + k0 + a_c0];
            sa1 = *(const float4*)&Ap[(long)(row0 + a_r1)*256 + k0 + a_c1];
            sb0 = *(const float4*)&Bw[(long)(k0 + b_r0)*N + col0 + b_c0];
            sb1 = *(const float4*)&Bw[(long)(k0 + b_r1)*N + col0 + b_c1];
        }

        #pragma unroll
        for (int kc = 0; kc < 16; kc += 8) {
            unsigned a[2][4], bf[8][2];
            #pragma unroll
            for (int mt = 0; mt < 2; mt++) {
                int rb = wm*32 + mt*16;
                a[mt][0] = As[cur][(rb + g    )*ASTR + kc + tg    ];
                a[mt][1] = As[cur][(rb + g + 8)*ASTR + kc + tg    ];
                a[mt][2] = As[cur][(rb + g    )*ASTR + kc + tg + 4];
                a[mt][3] = As[cur][(rb + g + 8)*ASTR + kc + tg + 4];
            }
            #pragma unroll
            for (int nt = 0; nt < 8; nt++) {
                int cb = wn*64 + nt*8;
                bf[nt][0] = Bs[cur][(kc + tg    )*BSTR + cb + g];
                bf[nt][1] = Bs[cur][(kc + tg + 4)*BSTR + cb + g];
            }
            #pragma unroll
            for (int mt = 0; mt < 2; mt++)
                #pragma unroll
                for (int nt = 0; nt < 8; nt++)
                    asm volatile(
                        "mma.sync.aligned.m16n8k8.row.col.f32.tf32.tf32.f32 "
                        "{%0,%1,%2,%3}, {%4,%5,%6,%7}, {%8,%9}, {%0,%1,%2,%3};"
                        : "+f"(c[mt][nt][0]), "+f"(c[mt][nt][1]),
                          "+f"(c[mt][nt][2]), "+f"(c[mt][nt][3])
                        : "r"(a[mt][0]), "r"(a[mt][1]), "r"(a[mt][2]), "r"(a[mt][3]),
                          "r"(bf[nt][0]), "r"(bf[nt][1]));
        }

        if (kt < NKT-1) {
            uint4 u;
            u.x=f2tf32(sa0.x); u.y=f2tf32(sa0.y); u.z=f2tf32(sa0.z); u.w=f2tf32(sa0.w);
            *(uint4*)&As[nxt][a_r0*ASTR + a_c0] = u;
            u.x=f2tf32(sa1.x); u.y=f2tf32(sa1.y); u.z=f2tf32(sa1.z); u.w=f2tf32(sa1.w);
            *(uint4*)&As[nxt][a_r1*ASTR + a_c1] = u;
            u.x=f2tf32(sb0.x); u.y=f2tf32(sb0.y); u.z=f2tf32(sb0.z); u.w=f2tf32(sb0.w);
            *(uint4*)&Bs[nxt][b_r0*BSTR + b_c0] = u;
            u.x=f2tf32(sb1.x); u.y=f2tf32(sb1.y); u.z=f2tf32(sb1.z); u.w=f2tf32(sb1.w);
            *(uint4*)&Bs[nxt][b_r1*BSTR + b_c1] = u;
        }
        __syncthreads();
    }

    // Epilogue
    #pragma unroll
    for (int mt = 0; mt < 2; mt++) {
        int r_lo = row0 + wm*32 + mt*16 + g;
        int r_hi = r_lo + 8;
        #pragma unroll
        for (int nt = 0; nt < 8; nt++) {
            int gj = col0 + wn*64 + nt*8 + 2*tg;
            float b0 = bias[gj], b1 = bias[gj+1];
            if (mode == 1) {
                Cout[(long)r_lo*N + gj    ] = c[mt][nt][0] + b0;
                Cout[(long)r_lo*N + gj + 1] = c[mt][nt][1] + b1;
                Cout[(long)r_hi*N + gj    ] = c[mt][nt][2] + b0;
                Cout[(long)r_hi*N + gj + 1] = c[mt][nt][3] + b1;
            } else {
                int t = gj >> 8;
                int h = (gj >> 5) & 7;
                int d = gj & 31;
                #pragma unroll
                for (int e = 0; e < 4; e++) {
                    int gm = (e < 2) ? r_lo : r_hi;
                    float v = c[mt][nt][e] + ((e & 1) ? b1 : b0);
                    int bb  = gm / POS;
                    int pos = gm % POS;
                    long off = ((long)(bb*NH + h)*POS + pos)*HD + d + (e & 1);
                    if (t == 0)       g_q[off] = v * QSCALE;
                    else if (t == 1)  g_k[off] = v;
                    else              g_v[off] = v;
                }
            }
        }
    }
}

// ---------------------------------------------------------------------------
// Tiled neighborhood attention — 256 threads (8 warps), 7 query rounds.
// ---------------------------------------------------------------------------
#define HALO 13
#define NROW (HALO*HALO)   // 169
#define KSTR 33

__global__ __launch_bounds__(256) void natten_kernel(const float* __restrict__ rpb0,
                                                     const float* __restrict__ rpb1)
{
    __shared__ alignas(16) float Ks[NROW*KSTR];
    __shared__ alignas(16) float Vs[NROW*HD];
    __shared__ alignas(16) float Rs[NROW];

    const int b = blockIdx.z;
    const int h = blockIdx.y;
    const int dil = (h < 4) ? 1 : 2;
    const float* __restrict__ rpb = (h < 4) ? (rpb0 + h*NROW) : (rpb1 + (h-4)*NROW);

    int ry, rx, qy0, qx0, L;
    if (dil == 1) {
        L = 56; ry = 0; rx = 0;
        qy0 = (blockIdx.x >> 3) * 7;
        qx0 = (blockIdx.x & 7) * 7;
    } else {
        L = 28;
        int sub = blockIdx.x >> 4;
        ry = sub >> 1; rx = sub & 1;
        int ti = blockIdx.x & 15;
        qy0 = (ti >> 2) * 7;
        qx0 = (ti & 3) * 7;
    }

    int hy0 = qy0 - 3; if (hy0 < 0) hy0 = 0; if (hy0 > L - HALO) hy0 = L - HALO;
    int hx0 = qx0 - 3; if (hx0 < 0) hx0 = 0; if (hx0 > L - HALO) hx0 = L - HALO;

    const long base = ((long)(b*NH + h)) * POS * HD;
    const int tid = threadIdx.x;

    // Halo load: 32 rows per 256-thread iteration
    {
        const int tr = tid >> 3;        // 0..31
        const int c  = (tid & 7) * 4;
        for (int t0 = 0; t0 < NROW; t0 += 32) {
            int t = t0 + tr;
            if (t < NROW) {
                int iy = t / HALO, ix = t % HALO;
                int gy = (hy0 + iy)*dil + ry;
                int gx = (hx0 + ix)*dil + rx;
                long off = base + (long)(gy*WW + gx)*HD + c;
                float4 kv = *(const float4*)&g_k[off];
                Ks[t*KSTR + c + 0] = kv.x;
                Ks[t*KSTR + c + 1] = kv.y;
                Ks[t*KSTR + c + 2] = kv.z;
                Ks[t*KSTR + c + 3] = kv.w;
                float4 vv = *(const float4*)&g_v[off];
                *(float4*)&Vs[t*HD + c] = vv;
            }
        }
    }
    for (int t = tid; t < NROW; t += 256) Rs[t] = rpb[t];
    __syncthreads();

    const int w    = tid >> 5;          // 0..7
    const int lane = tid & 31;

    const int n1 = lane;
    const int i1 = n1 / 7, j1 = n1 % 7;
    const bool has2 = (lane < 17);
    const int n2 = 32 + lane;
    const int i2 = has2 ? n2 / 7 : 0;
    const int j2 = has2 ? n2 % 7 : 0;

    #pragma unroll
    for (int t = 0; t < 7; t++) {
        int q = w + 8*t;
        if (q >= 49) break;
        int qy = qy0 + q / 7;
        int qx = qx0 + q % 7;

        int wsy = qy - 3; if (wsy < 0) wsy = 0; if (wsy > L-7) wsy = L-7;
        int wsx = qx - 3; if (wsx < 0) wsx = 0; if (wsx > L-7) wsx = L-7;
        int oy = wsy - hy0, ox = wsx - hx0;
        int biy = wsy - qy + 6, bix = wsx - qx + 6;

        int gy = qy*dil + ry;
        int gx = qx*dil + rx;

        float qreg = g_q[base + (long)(gy*WW + gx)*HD + lane];

        const float* k1 = &Ks[((oy + i1)*HALO + ox + j1) * KSTR];
        const float* k2 = &Ks[((oy + i2)*HALO + ox + j2) * KSTR];

        float a1 = 0.0f, a2 = 0.0f;
        #pragma unroll
        for (int d = 0; d < 32; d++) {
            float qd = __shfl_sync(0xffffffffu, qreg, d);
            a1 += qd * k1[d];
            a2 += qd * k2[d];
        }

        float l0 = a1 + Rs[(biy + i1)*HALO + bix + j1];
        float l1 = has2 ? (a2 + Rs[(biy + i2)*HALO + bix + j2]) : -1e30f;

        float mx = fmaxf(l0, l1);
        #pragma unroll
        for (int s = 16; s; s >>= 1)
            mx = fmaxf(mx, __shfl_xor_sync(0xffffffffu, mx, s));

        float p0 = __expf(l0 - mx);
        float p1 = has2 ? __expf(l1 - mx) : 0.0f;

        float sum = p0 + p1;
        #pragma unroll
        for (int s = 16; s; s >>= 1)
            sum += __shfl_xor_sync(0xffffffffu, sum, s);
        float inv = 1.0f / sum;

        float acc = 0.0f;
        #pragma unroll
        for (int n = 0; n < 49; n++) {
            const int ni = n / 7, nj = n % 7;
            int rr = (oy + ni)*HALO + ox + nj;
            float pv = (n < 32) ? p0 : p1;
            float p = __shfl_sync(0xffffffffu, pv, n & 31);
            acc += p * Vs[rr*HD + lane];
        }

        g_att[((long)(b*POS) + gy*WW + gx)*C_ + h*HD + lane] = acc * inv;
    }
}

// ---------------------------------------------------------------------------
extern "C" void kernel_launch(void* const* d_in, const int* in_sizes, int n_in,
                              void* d_out, int out_size)
{
    const float* x      = (const float*)d_in[0];
    const float* w_qkv  = (const float*)d_in[1];
    const float* b_qkv  = (const float*)d_in[2];
    const float* w_proj = (const float*)d_in[3];
    const float* b_proj = (const float*)d_in[4];
    const float* rpb0   = (const float*)d_in[5];
    const float* rpb1   = (const float*)d_in[6];
    float* out = (float*)d_out;

    dim3 blk(256);
    dim3 grid_qkv((3*C_)/128, TOK/128);   // (6, 49)
    dim3 grid_proj(C_/128,    TOK/128);   // (2, 49)

    gemm_tf32_kernel<<<grid_qkv, blk>>>(x, w_qkv, b_qkv, nullptr, 3*C_, 0);
    natten_kernel<<<dim3(64, NH, B_), 256>>>(rpb0, rpb1);
    gemm_tf32_kernel<<<grid_proj, blk>>>(nullptr, w_proj, b_proj, out, C_, 1);
}